// round 8
// baseline (speedup 1.0000x reference)
#include <cuda_runtime.h>

// ExpandEvecs: out[b,k,n,m] = sum_{j<=k} ev[b,n,j] * ev[b,m,j]
// ev: [4,1,1024,16] fp32 ; out: [4,16,1024,1024] fp32 (256 MB)
// At the HBM pure-write ceiling (~4.5-5.2 TB/s). This round combines the two
// best measured configs:
//  - grid 256 (one full wave at occ 2, zero wave-2 tail)  [R1: best kernel dur]
//  - k-outer store order, 8 consecutive rows per plane-visit = 32KB
//    contiguous CTA bursts                                  [R7: best wall]
// CTA covers 16 n-rows as two sequential 8-row half-tiles so the 8 running
// cumsum accumulators + 4 register-resident B-rows fit in ~112 regs.

#define NDIM 1024
#define KDIM 16
#define TILE_N 16
#define HALF_N 8

__global__ __launch_bounds__(256, 2)
void expand_evecs_kernel(const float* __restrict__ ev, float* __restrict__ out) {
    const int b   = blockIdx.y;
    const int n0  = blockIdx.x * TILE_N;
    const int tid = threadIdx.x;
    const int m   = tid << 2;                 // 4 consecutive m-cols per thread

    __shared__ float a_s[TILE_N][KDIM];       // 16 x 16 a-rows for this n-tile

    const float* evb = ev + (size_t)b * NDIM * KDIM;

    // Load a-tile: 256 contiguous floats, one per thread.
    a_s[tid >> 4][tid & 15] = evb[(size_t)n0 * KDIM + tid];

    // This thread's 4 B-rows, register-resident for the whole block.
    float bw[4][KDIM];
    const float4* evb4 = (const float4*)evb;
    #pragma unroll
    for (int i = 0; i < 4; ++i) {
        #pragma unroll
        for (int q = 0; q < 4; ++q)
            ((float4*)bw[i])[q] = evb4[(size_t)(m + i) * (KDIM / 4) + q];
    }
    __syncthreads();

    const size_t plane = (size_t)NDIM * NDIM;

    #pragma unroll 1
    for (int h = 0; h < 2; ++h) {             // two 8-row half-tiles
        const int nh = h * HALF_N;

        float4 acc[HALF_N];
        #pragma unroll
        for (int nn = 0; nn < HALF_N; ++nn)
            acc[nn] = make_float4(0.f, 0.f, 0.f, 0.f);

        // Base pointer: plane k=0, row n0+nh, col m.
        float* op = out + (((size_t)b * KDIM) * NDIM + (n0 + nh)) * NDIM + m;

        #pragma unroll
        for (int k = 0; k < KDIM; ++k) {
            // 8 consecutive 4KB rows of plane k -> 32KB contiguous burst.
            #pragma unroll
            for (int nn = 0; nn < HALF_N; ++nn) {
                const float ak = a_s[nh + nn][k];   // LDS broadcast
                acc[nn].x = fmaf(ak, bw[0][k], acc[nn].x);
                acc[nn].y = fmaf(ak, bw[1][k], acc[nn].y);
                acc[nn].z = fmaf(ak, bw[2][k], acc[nn].z);
                acc[nn].w = fmaf(ak, bw[3][k], acc[nn].w);
                *(float4*)(op + (size_t)nn * NDIM) = acc[nn];
            }
            op += plane;
        }
    }
}

extern "C" void kernel_launch(void* const* d_in, const int* in_sizes, int n_in,
                              void* d_out, int out_size) {
    const float* ev = (const float*)d_in[0];
    float* out = (float*)d_out;
    const int B = in_sizes[0] / (NDIM * KDIM);   // = 4
    dim3 grid(NDIM / TILE_N, B);                 // 64 x 4 = 256 blocks, one wave
    expand_evecs_kernel<<<grid, 256>>>(ev, out);
}

// round 9
// speedup vs baseline: 1.3351x; 1.3351x over previous
#include <cuda_runtime.h>

// ExpandEvecs: out[b,k,n,m] = sum_{j<=k} ev[b,n,j] * ev[b,m,j]
// ev: [4,1,1024,16] fp32 ; out: [4,16,1024,1024] fp32 (256 MB)
// Near the HBM pure-write ceiling. R9: R8's plan without register spills.
//  - B-panel transposed into smem: sm_b[k][m] (64 KB). Per k, a thread does
//    ONE conflict-free LDS.128 instead of holding 64 B-regs -> regs ~85.
//  - a-values are broadcasts from the same array: sm_b[k][n0+nn].
//  - k-outer, 16 running float4 accumulators -> each CTA writes 16
//    consecutive rows (64 KB contiguous) per k-plane visit.
//  - grid 256 = one full wave at occ 2, zero tail.

#define NDIM 1024
#define KDIM 16
#define TILE_N 16
#define PADN (NDIM + 4)   // row stride 4112 B: breaks bank aliasing, 16B-aligned

__global__ __launch_bounds__(256, 2)
void expand_evecs_kernel(const float* __restrict__ ev, float* __restrict__ out) {
    __shared__ float sm_b[KDIM][PADN];        // transposed B-panel, 64.25 KB

    const int b   = blockIdx.y;
    const int n0  = blockIdx.x * TILE_N;
    const int tid = threadIdx.x;
    const int m   = tid << 2;                 // 4 consecutive m-cols per thread

    const float* evb = ev + (size_t)b * NDIM * KDIM;

    // Cooperative transpose load: sm_b[k][mm] = evb[mm*16 + k].
    // Coalesced 128B global reads; smem scatter (one-time, 64KB, negligible).
    for (int idx = tid; idx < NDIM * KDIM; idx += 256) {
        const int mm = idx >> 4;
        const int k  = idx & 15;
        sm_b[k][mm] = evb[idx];
    }
    __syncthreads();

    // 16 running cumsum accumulators, one per n-row of the tile.
    float4 acc[TILE_N];
    #pragma unroll
    for (int nn = 0; nn < TILE_N; ++nn)
        acc[nn] = make_float4(0.f, 0.f, 0.f, 0.f);

    float* op = out + (((size_t)b * KDIM) * NDIM + n0) * NDIM + m;
    const size_t plane = (size_t)NDIM * NDIM;

    #pragma unroll
    for (int k = 0; k < KDIM; ++k) {
        // This thread's 4 B-values for step k: one conflict-free LDS.128.
        const float4 vb = *(const float4*)&sm_b[k][m];

        // 16 consecutive 4KB rows of plane k -> 64KB contiguous CTA burst.
        #pragma unroll
        for (int nn = 0; nn < TILE_N; ++nn) {
            const float ak = sm_b[k][n0 + nn];    // LDS broadcast
            acc[nn].x = fmaf(ak, vb.x, acc[nn].x);
            acc[nn].y = fmaf(ak, vb.y, acc[nn].y);
            acc[nn].z = fmaf(ak, vb.z, acc[nn].z);
            acc[nn].w = fmaf(ak, vb.w, acc[nn].w);
            *(float4*)(op + (size_t)nn * NDIM) = acc[nn];
        }
        op += plane;
    }
}

extern "C" void kernel_launch(void* const* d_in, const int* in_sizes, int n_in,
                              void* d_out, int out_size) {
    const float* ev = (const float*)d_in[0];
    float* out = (float*)d_out;
    const int B = in_sizes[0] / (NDIM * KDIM);   // = 4
    dim3 grid(NDIM / TILE_N, B);                 // 64 x 4 = 256 blocks, one wave
    expand_evecs_kernel<<<grid, 256>>>(ev, out);
}

// round 10
// speedup vs baseline: 1.4378x; 1.0769x over previous
#include <cuda_runtime.h>

// ExpandEvecs: out[b,k,n,m] = sum_{j<=k} ev[b,n,j] * ev[b,m,j]
// ev: [4,1,1024,16] fp32 ; out: [4,16,1024,1024] fp32 (256 MB)
// Wall time = 256MB / ~5.2 TB/s steady-state HBM write drain across ALL
// configs. This round: R7's best-measured structure (k-outer, 8-row tiles,
// 32KB contiguous bursts, grid 512, occ 2) with ONE delta: write-through
// stores (__stwt). WT streams data to DRAM as produced instead of building
// a dirty-L2 bulge that must drain between graph replays.

#define NDIM 1024
#define KDIM 16
#define TILE_N 8

__global__ __launch_bounds__(256, 2)
void expand_evecs_kernel(const float* __restrict__ ev, float* __restrict__ out) {
    const int b   = blockIdx.y;
    const int n0  = blockIdx.x * TILE_N;
    const int tid = threadIdx.x;
    const int m   = tid << 2;                 // 4 consecutive m-cols per thread

    __shared__ float a_s[TILE_N][KDIM];       // 8 x 16 a-rows for this n-tile

    const float* evb = ev + (size_t)b * NDIM * KDIM;

    // Load a-tile: 128 contiguous floats.
    if (tid < TILE_N * KDIM)
        a_s[tid >> 4][tid & 15] = evb[(size_t)n0 * KDIM + tid];

    // This thread's 4 B-rows, register-resident.
    float bw[4][KDIM];
    const float4* evb4 = (const float4*)evb;
    #pragma unroll
    for (int i = 0; i < 4; ++i) {
        #pragma unroll
        for (int q = 0; q < 4; ++q)
            ((float4*)bw[i])[q] = evb4[(size_t)(m + i) * (KDIM / 4) + q];
    }
    __syncthreads();

    // 8 running cumsum accumulators, one per n-row in the tile.
    float4 acc[TILE_N];
    #pragma unroll
    for (int nn = 0; nn < TILE_N; ++nn)
        acc[nn] = make_float4(0.f, 0.f, 0.f, 0.f);

    // Base pointer: plane k=0, row n0, col m.
    float* op = out + (((size_t)b * KDIM) * NDIM + n0) * NDIM + m;
    const size_t plane = (size_t)NDIM * NDIM;

    #pragma unroll
    for (int k = 0; k < KDIM; ++k) {
        // 8 consecutive 4KB rows of plane k -> 32KB contiguous CTA burst.
        #pragma unroll
        for (int nn = 0; nn < TILE_N; ++nn) {
            const float ak = a_s[nn][k];      // LDS broadcast
            acc[nn].x = fmaf(ak, bw[0][k], acc[nn].x);
            acc[nn].y = fmaf(ak, bw[1][k], acc[nn].y);
            acc[nn].z = fmaf(ak, bw[2][k], acc[nn].z);
            acc[nn].w = fmaf(ak, bw[3][k], acc[nn].w);
            __stwt((float4*)(op + (size_t)nn * NDIM), acc[nn]);   // write-through
        }
        op += plane;
    }
}

extern "C" void kernel_launch(void* const* d_in, const int* in_sizes, int n_in,
                              void* d_out, int out_size) {
    const float* ev = (const float*)d_in[0];
    float* out = (float*)d_out;
    const int B = in_sizes[0] / (NDIM * KDIM);   // = 4
    dim3 grid(NDIM / TILE_N, B);                 // 128 x 4 = 512 blocks
    expand_evecs_kernel<<<grid, 256>>>(ev, out);
}

// round 11
// speedup vs baseline: 1.4641x; 1.0183x over previous
#include <cuda_runtime.h>

// ExpandEvecs: out[b,k,n,m] = sum_{j<=k} ev[b,n,j] * ev[b,m,j]
// ev: [4,1,1024,16] fp32 ; out: [4,16,1024,1024] fp32 (256 MB)
// Wall time = 256MB / ~5.2 TB/s steady-state HBM write drain across ALL
// configs. This round: R7's best-measured structure (k-outer, 8-row tiles,
// 32KB contiguous bursts, grid 512, occ 2) with ONE delta: write-through
// stores (__stwt). WT streams data to DRAM as produced instead of building
// a dirty-L2 bulge that must drain between graph replays.

#define NDIM 1024
#define KDIM 16
#define TILE_N 8

__global__ __launch_bounds__(256, 2)
void expand_evecs_kernel(const float* __restrict__ ev, float* __restrict__ out) {
    const int b   = blockIdx.y;
    const int n0  = blockIdx.x * TILE_N;
    const int tid = threadIdx.x;
    const int m   = tid << 2;                 // 4 consecutive m-cols per thread

    __shared__ float a_s[TILE_N][KDIM];       // 8 x 16 a-rows for this n-tile

    const float* evb = ev + (size_t)b * NDIM * KDIM;

    // Load a-tile: 128 contiguous floats.
    if (tid < TILE_N * KDIM)
        a_s[tid >> 4][tid & 15] = evb[(size_t)n0 * KDIM + tid];

    // This thread's 4 B-rows, register-resident.
    float bw[4][KDIM];
    const float4* evb4 = (const float4*)evb;
    #pragma unroll
    for (int i = 0; i < 4; ++i) {
        #pragma unroll
        for (int q = 0; q < 4; ++q)
            ((float4*)bw[i])[q] = evb4[(size_t)(m + i) * (KDIM / 4) + q];
    }
    __syncthreads();

    // 8 running cumsum accumulators, one per n-row in the tile.
    float4 acc[TILE_N];
    #pragma unroll
    for (int nn = 0; nn < TILE_N; ++nn)
        acc[nn] = make_float4(0.f, 0.f, 0.f, 0.f);

    // Base pointer: plane k=0, row n0, col m.
    float* op = out + (((size_t)b * KDIM) * NDIM + n0) * NDIM + m;
    const size_t plane = (size_t)NDIM * NDIM;

    #pragma unroll
    for (int k = 0; k < KDIM; ++k) {
        // 8 consecutive 4KB rows of plane k -> 32KB contiguous CTA burst.
        #pragma unroll
        for (int nn = 0; nn < TILE_N; ++nn) {
            const float ak = a_s[nn][k];      // LDS broadcast
            acc[nn].x = fmaf(ak, bw[0][k], acc[nn].x);
            acc[nn].y = fmaf(ak, bw[1][k], acc[nn].y);
            acc[nn].z = fmaf(ak, bw[2][k], acc[nn].z);
            acc[nn].w = fmaf(ak, bw[3][k], acc[nn].w);
            __stwt((float4*)(op + (size_t)nn * NDIM), acc[nn]);   // write-through
        }
        op += plane;
    }
}

extern "C" void kernel_launch(void* const* d_in, const int* in_sizes, int n_in,
                              void* d_out, int out_size) {
    const float* ev = (const float*)d_in[0];
    float* out = (float*)d_out;
    const int B = in_sizes[0] / (NDIM * KDIM);   // = 4
    dim3 grid(NDIM / TILE_N, B);                 // 128 x 4 = 512 blocks
    expand_evecs_kernel<<<grid, 256>>>(ev, out);
}